// round 12
// baseline (speedup 1.0000x reference)
#include <cuda_runtime.h>
#include <cuda_fp16.h>
#include <cstdint>

#define DIMC 1024
#define HEADS 16
#define DH 64
#define BATCHB 4
#define SEQN 2048
#define MROWS (BATCHB * SEQN)
#define SCALE 0.125f
#define LOG2E 1.4426950408889634f

// Scratch (no allocations allowed)
__device__ __half g_xh[(size_t)MROWS * DIMC];
__device__ __half g_wqh[(size_t)3 * DIMC * DIMC];
__device__ __half g_wfh[(size_t)DIMC * DIMC];
__device__ __half g_qkvh[(size_t)MROWS * 3 * DIMC];
__device__ __half g_xah[(size_t)MROWS * DIMC];

// ---------------- PTX helpers ----------------
__device__ __forceinline__ void mma16816(float* d, const uint32_t* a, uint32_t b0, uint32_t b1) {
    asm volatile(
        "mma.sync.aligned.m16n8k16.row.col.f32.f16.f16.f32 "
        "{%0,%1,%2,%3}, {%4,%5,%6,%7}, {%8,%9}, {%0,%1,%2,%3};"
        : "+f"(d[0]), "+f"(d[1]), "+f"(d[2]), "+f"(d[3])
        : "r"(a[0]), "r"(a[1]), "r"(a[2]), "r"(a[3]),
          "r"(b0), "r"(b1));
}
__device__ __forceinline__ void ldsm_x4(uint32_t* r, uint32_t addr) {
    asm volatile("ldmatrix.sync.aligned.m8n8.x4.shared.b16 {%0,%1,%2,%3}, [%4];"
                 : "=r"(r[0]), "=r"(r[1]), "=r"(r[2]), "=r"(r[3]) : "r"(addr));
}
__device__ __forceinline__ void ldsm_x4_t(uint32_t& r0, uint32_t& r1, uint32_t& r2, uint32_t& r3,
                                          uint32_t addr) {
    asm volatile("ldmatrix.sync.aligned.m8n8.x4.trans.shared.b16 {%0,%1,%2,%3}, [%4];"
                 : "=r"(r0), "=r"(r1), "=r"(r2), "=r"(r3) : "r"(addr));
}
__device__ __forceinline__ float ex2f(float x) {
    float y;
    asm("ex2.approx.ftz.f32 %0, %1;" : "=f"(y) : "f"(x));
    return y;
}
__device__ __forceinline__ uint32_t packh2(float lo, float hi) {
    __half2 h = __floats2half2_rn(lo, hi);
    return *(uint32_t*)&h;
}
__device__ __forceinline__ void cp16(uint32_t dst, const void* src) {
    asm volatile("cp.async.cg.shared.global [%0], [%1], 16;" :: "r"(dst), "l"(src) : "memory");
}
#define CP_COMMIT() asm volatile("cp.async.commit_group;" ::: "memory")
#define CP_WAIT0()  asm volatile("cp.async.wait_group 0;" ::: "memory")
#define CP_WAIT1()  asm volatile("cp.async.wait_group 1;" ::: "memory")

// ---------------------------------------------------------------------------
// fp32 -> fp16 conversion pass
// ---------------------------------------------------------------------------
__global__ __launch_bounds__(256) void cvt_fp16(const float* __restrict__ in,
                                                __half* __restrict__ out, int n)
{
    int i = (blockIdx.x * 256 + threadIdx.x) * 4;
    if (i >= n) return;
    float4 v = *(const float4*)(in + i);
    uint2 o;
    o.x = packh2(v.x, v.y);
    o.y = packh2(v.z, v.w);
    *(uint2*)(out + i) = o;
}

// ---------------------------------------------------------------------------
// fp16 GEMM: C[m,n] = sum_k A[m,k]*B[n,k] (+bias). K = 1024 fixed.
// Block 128x128, BK=32, 256 threads (8 warps as 2m x 4n), warp tile 64x32.
// 3-stage cp.async pipeline (R8 best-known). Per chunk: ALL 12 LDSM hoisted
// ahead of all 32 MMAs (one exposed LDSM window/chunk instead of two).
// launch_bounds(256,2) pins the 2-CTA register budget (<=128).
// ---------------------------------------------------------------------------
#define GST     20480   // bytes per stage (A 10240 + B 10240)
#define GSMEM   (3 * GST)   // 61440

template <bool OUT_HALF>
__global__ __launch_bounds__(256, 2) void gemm_h(const __half* __restrict__ A,
                                                 const __half* __restrict__ B,
                                                 void* __restrict__ Cout,
                                                 const float* __restrict__ bias,
                                                 int N)
{
    extern __shared__ unsigned char sm[];
    const uint32_t smb = (uint32_t)__cvta_generic_to_shared(sm);
    const int tid  = threadIdx.x;
    const int wid  = tid >> 5;
    const int lane = tid & 31;
    const int g    = lane >> 2;
    const int tg   = lane & 3;
    const int bm   = blockIdx.y * 128;
    const int bn   = blockIdx.x * 128;
    const int wm   = (wid >> 2) * 64;
    const int wn   = (wid & 3) * 32;

    // staging map: thread -> row (tid>>1), two 16B chunks at (tid&1)*2
    const int r   = tid >> 1;
    const int ch0 = (tid & 1) * 2;
    const __half* Ap = A + (size_t)(bm + r) * DIMC + ch0 * 8;
    const __half* Bp = B + (size_t)(bn + r) * DIMC + ch0 * 8;
    const uint32_t dA = smb + (uint32_t)(r * 80 + ch0 * 16);
    const uint32_t dB = dA + 10240;

    float acc[4][4][4];
#pragma unroll
    for (int mt = 0; mt < 4; mt++)
#pragma unroll
        for (int nt = 0; nt < 4; nt++)
#pragma unroll
            for (int i = 0; i < 4; i++) acc[mt][nt][i] = 0.0f;

    // prologue: stage chunks 0,1
#pragma unroll
    for (int c = 0; c < 2; c++) {
        cp16(dA + c * GST,      Ap + c * 32);
        cp16(dA + c * GST + 16, Ap + c * 32 + 8);
        cp16(dB + c * GST,      Bp + c * 32);
        cp16(dB + c * GST + 16, Bp + c * 32 + 8);
        CP_COMMIT();
    }

    // per-lane ldmatrix base offsets (stage-relative)
    const uint32_t aoff = (uint32_t)((wm + (lane & 15)) * 80 + (lane >> 4) * 16);
    const uint32_t boff = (uint32_t)(10240 + (wn + (lane & 7) + (lane >> 4) * 8) * 80 +
                                     ((lane >> 3) & 1) * 16);

    for (int c = 0; c < 32; c++) {
        const int s = c % 3;
        if (c == 31) { CP_WAIT0(); } else { CP_WAIT1(); }
        __syncthreads();
        if (c + 2 < 32) {
            const int sn = (c + 2) % 3;
            const __half* sa = Ap + (c + 2) * 32;
            const __half* sb = Bp + (c + 2) * 32;
            cp16(dA + sn * GST,      sa);
            cp16(dA + sn * GST + 16, sa + 8);
            cp16(dB + sn * GST,      sb);
            cp16(dB + sn * GST + 16, sb + 8);
            CP_COMMIT();
        }
        const uint32_t sb32 = smb + (uint32_t)(s * GST);

        // hoist ALL fragment loads for the chunk, then all MMAs
        uint32_t af[2][4][4], bf[2][2][4];
#pragma unroll
        for (int ks = 0; ks < 2; ks++) {
#pragma unroll
            for (int mt = 0; mt < 4; mt++)
                ldsm_x4(af[ks][mt], sb32 + aoff + mt * 1280 + ks * 32);
#pragma unroll
            for (int p = 0; p < 2; p++)
                ldsm_x4(bf[ks][p], sb32 + boff + p * 1280 + ks * 32);
        }
#pragma unroll
        for (int ks = 0; ks < 2; ks++)
#pragma unroll
            for (int mt = 0; mt < 4; mt++)
#pragma unroll
                for (int nt = 0; nt < 4; nt++)
                    mma16816(acc[mt][nt], af[ks][mt],
                             bf[ks][nt >> 1][(nt & 1) * 2], bf[ks][nt >> 1][(nt & 1) * 2 + 1]);
    }

    // epilogue
#pragma unroll
    for (int mt = 0; mt < 4; mt++) {
#pragma unroll
        for (int nt = 0; nt < 4; nt++) {
            const int row0 = bm + wm + mt * 16 + g;
            const int col  = bn + wn + nt * 8 + 2 * tg;
            if (OUT_HALF) {
                __half* C = (__half*)Cout;
                *(uint32_t*)&C[(size_t)row0 * N + col]       = packh2(acc[mt][nt][0], acc[mt][nt][1]);
                *(uint32_t*)&C[(size_t)(row0 + 8) * N + col] = packh2(acc[mt][nt][2], acc[mt][nt][3]);
            } else {
                float* C = (float*)Cout;
                float b0 = 0.0f, b1 = 0.0f;
                if (bias != nullptr) { b0 = bias[col]; b1 = bias[col + 1]; }
                float2 v0, v1;
                v0.x = acc[mt][nt][0] + b0; v0.y = acc[mt][nt][1] + b1;
                v1.x = acc[mt][nt][2] + b0; v1.y = acc[mt][nt][3] + b1;
                *(float2*)(C + (size_t)row0 * N + col)       = v0;
                *(float2*)(C + (size_t)(row0 + 8) * N + col) = v1;
            }
        }
    }
}

// ---------------------------------------------------------------------------
// Flash attention, fp16 MMA, 2-stage cp.async KV pipeline (best-known).
// Block = (b, h, 128 q-rows). 8 warps x 16 q-rows. 64-key tiles.
// ---------------------------------------------------------------------------
#define KVBUF 9216   // 64*72*2 bytes per buffer

__global__ __launch_bounds__(256, 2) void attn_fa16(const __half* __restrict__ qkvh,
                                                    const int* __restrict__ pmask,
                                                    __half* __restrict__ xout)
{
    __shared__ __half Ks[2][64][72];
    __shared__ __half Vs[2][64][72];
    __shared__ float  mb[2][64];

    const int t    = threadIdx.x;
    const int w    = t >> 5;
    const int lane = t & 31;
    const int g    = lane >> 2;
    const int tg   = lane & 3;
    const int h    = blockIdx.y;
    const int b    = blockIdx.z;
    const int qbase = blockIdx.x * 128;

    const float SC2 = SCALE * LOG2E;

    uint32_t qa[4][4];
    {
        const int qr = b * SEQN + qbase + w * 16 + g;
        const __half* q0 = qkvh + (size_t)qr * (3 * DIMC) + h * DH;
        const __half* q8 = q0 + (size_t)8 * (3 * DIMC);
#pragma unroll
        for (int kt = 0; kt < 4; kt++) {
            qa[kt][0] = *(const uint32_t*)(q0 + kt * 16 + 2 * tg);
            qa[kt][1] = *(const uint32_t*)(q8 + kt * 16 + 2 * tg);
            qa[kt][2] = *(const uint32_t*)(q0 + kt * 16 + 8 + 2 * tg);
            qa[kt][3] = *(const uint32_t*)(q8 + kt * 16 + 8 + 2 * tg);
        }
    }

    const int lr = ((lane >> 3) & 1) * 8 + (lane & 7);
    const int lc = (lane >> 4) * 8;
    const uint32_t kbase = (uint32_t)__cvta_generic_to_shared(&Ks[0][0][0]);
    const uint32_t vbase = (uint32_t)__cvta_generic_to_shared(&Vs[0][0][0]);

    float m0 = -1e30f, m1 = -1e30f, l0 = 0.0f, l1 = 0.0f;
    float of[8][4];
#pragma unroll
    for (int nt = 0; nt < 8; nt++)
#pragma unroll
        for (int i = 0; i < 4; i++) of[nt][i] = 0.0f;

    const int rk  = t >> 2;
    const int chk = (t & 3) * 2;
    const uint32_t dK = kbase + (uint32_t)(rk * 144 + chk * 16);
    const uint32_t dV = vbase + (uint32_t)(rk * 144 + chk * 16);
    const __half* kvsrc = qkvh + (size_t)(b * SEQN + rk) * (3 * DIMC) + DIMC + h * DH + chk * 8;

    // prologue: stage tile 0 into buffer 0
    cp16(dK,      kvsrc);
    cp16(dK + 16, kvsrc + 8);
    cp16(dV,      kvsrc + DIMC);
    cp16(dV + 16, kvsrc + DIMC + 8);
    CP_COMMIT();
    if (t < 64) mb[0][t] = (pmask[b * SEQN + t] > 0) ? -1e9f : 0.0f;

    for (int it = 0; it < SEQN / 64; it++) {
        const int cur = it & 1;
        const int nxt = cur ^ 1;
        const bool have_next = (it + 1 < SEQN / 64);

        __syncthreads();
        if (have_next) {
            const __half* src = kvsrc + (size_t)(it + 1) * 64 * (3 * DIMC);
            const uint32_t o = (uint32_t)(nxt * KVBUF);
            cp16(dK + o,      src);
            cp16(dK + o + 16, src + 8);
            cp16(dV + o,      src + DIMC);
            cp16(dV + o + 16, src + DIMC + 8);
            CP_COMMIT();
            if (t < 64) mb[nxt][t] = (pmask[b * SEQN + (it + 1) * 64 + t] > 0) ? -1e9f : 0.0f;
        }
        if (have_next) { CP_WAIT1(); } else { CP_WAIT0(); }
        __syncthreads();

        float sf[8][4];
#pragma unroll
        for (int nt = 0; nt < 8; nt++)
#pragma unroll
            for (int i = 0; i < 4; i++) sf[nt][i] = 0.0f;
#pragma unroll
        for (int kt = 0; kt < 4; kt++) {
#pragma unroll
            for (int nt = 0; nt < 8; nt++) {
                uint32_t kb0 = *(const uint32_t*)&Ks[cur][8 * nt + g][16 * kt + 2 * tg];
                uint32_t kb1 = *(const uint32_t*)&Ks[cur][8 * nt + g][16 * kt + 2 * tg + 8];
                mma16816(sf[nt], qa[kt], kb0, kb1);
            }
        }

        float mt0 = -1e30f, mt1 = -1e30f;
#pragma unroll
        for (int nt = 0; nt < 8; nt++) {
            float2 bb = *(const float2*)&mb[cur][8 * nt + 2 * tg];
            sf[nt][0] = fmaf(sf[nt][0], SC2, bb.x);
            sf[nt][1] = fmaf(sf[nt][1], SC2, bb.y);
            sf[nt][2] = fmaf(sf[nt][2], SC2, bb.x);
            sf[nt][3] = fmaf(sf[nt][3], SC2, bb.y);
            mt0 = fmaxf(mt0, fmaxf(sf[nt][0], sf[nt][1]));
            mt1 = fmaxf(mt1, fmaxf(sf[nt][2], sf[nt][3]));
        }
        mt0 = fmaxf(mt0, __shfl_xor_sync(0xffffffffu, mt0, 1));
        mt0 = fmaxf(mt0, __shfl_xor_sync(0xffffffffu, mt0, 2));
        mt1 = fmaxf(mt1, __shfl_xor_sync(0xffffffffu, mt1, 1));
        mt1 = fmaxf(mt1, __shfl_xor_sync(0xffffffffu, mt1, 2));

        const float mn0 = fmaxf(m0, mt0);
        const float mn1 = fmaxf(m1, mt1);
        const float alpha0 = ex2f(m0 - mn0);
        const float alpha1 = ex2f(m1 - mn1);
        m0 = mn0; m1 = mn1;

        float ls0 = 0.0f, ls1 = 0.0f;
        uint32_t pa[4][4];
#pragma unroll
        for (int nt = 0; nt < 8; nt++) {
            float p0 = ex2f(sf[nt][0] - mn0);
            float p1 = ex2f(sf[nt][1] - mn0);
            float p2 = ex2f(sf[nt][2] - mn1);
            float p3 = ex2f(sf[nt][3] - mn1);
            ls0 += p0 + p1;
            ls1 += p2 + p3;
            const int kt = nt >> 1;
            const int hi = (nt & 1) ? 2 : 0;
            pa[kt][hi + 0] = packh2(p0, p1);
            pa[kt][hi + 1] = packh2(p2, p3);
        }
        l0 = l0 * alpha0 + ls0;
        l1 = l1 * alpha1 + ls1;
#pragma unroll
        for (int nt = 0; nt < 8; nt++) {
            of[nt][0] *= alpha0;
            of[nt][1] *= alpha0;
            of[nt][2] *= alpha1;
            of[nt][3] *= alpha1;
        }

        const uint32_t vb = vbase + (uint32_t)(cur * KVBUF);
#pragma unroll
        for (int kt = 0; kt < 4; kt++) {
#pragma unroll
            for (int c = 0; c < 8; c += 2) {
                uint32_t r0, r1, r2, r3;
                uint32_t addr = vb + (uint32_t)(((16 * kt + lr) * 72 + lc + 8 * c) * 2);
                ldsm_x4_t(r0, r1, r2, r3, addr);
                mma16816(of[c],     pa[kt], r0, r1);
                mma16816(of[c + 1], pa[kt], r2, r3);
            }
        }
    }

    l0 += __shfl_xor_sync(0xffffffffu, l0, 1);
    l0 += __shfl_xor_sync(0xffffffffu, l0, 2);
    l1 += __shfl_xor_sync(0xffffffffu, l1, 1);
    l1 += __shfl_xor_sync(0xffffffffu, l1, 2);
    const float inv0 = 1.0f / l0;
    const float inv1 = 1.0f / l1;

    const int qr = qbase + w * 16 + g;
    __half* o0 = xout + ((size_t)(b * SEQN + qr) * HEADS + h) * DH;
    __half* o8 = xout + ((size_t)(b * SEQN + qr + 8) * HEADS + h) * DH;
#pragma unroll
    for (int nt = 0; nt < 8; nt++) {
        *(uint32_t*)&o0[8 * nt + 2 * tg] = packh2(of[nt][0] * inv0, of[nt][1] * inv0);
        *(uint32_t*)&o8[8 * nt + 2 * tg] = packh2(of[nt][2] * inv1, of[nt][3] * inv1);
    }
}

// ---------------------------------------------------------------------------
extern "C" void kernel_launch(void* const* d_in, const int* in_sizes, int n_in,
                              void* d_out, int out_size)
{
    const float* x     = (const float*)d_in[0];
    const float* Wqkv  = (const float*)d_in[1];
    const float* Wfc   = (const float*)d_in[2];
    const float* bfc   = (const float*)d_in[3];
    const int*   pmask = (const int*)d_in[4];
    float* out = (float*)d_out;

    __half *xh, *wqh, *wfh, *qkvh, *xah;
    cudaGetSymbolAddress((void**)&xh, g_xh);
    cudaGetSymbolAddress((void**)&wqh, g_wqh);
    cudaGetSymbolAddress((void**)&wfh, g_wfh);
    cudaGetSymbolAddress((void**)&qkvh, g_qkvh);
    cudaGetSymbolAddress((void**)&xah, g_xah);

    cudaFuncSetAttribute(gemm_h<true>,  cudaFuncAttributeMaxDynamicSharedMemorySize, GSMEM);
    cudaFuncSetAttribute(gemm_h<false>, cudaFuncAttributeMaxDynamicSharedMemorySize, GSMEM);

    // 0) fp32 -> fp16 conversion passes
    cvt_fp16<<<(MROWS * DIMC) / 1024, 256>>>(x, xh, MROWS * DIMC);
    cvt_fp16<<<(3 * DIMC * DIMC) / 1024, 256>>>(Wqkv, wqh, 3 * DIMC * DIMC);
    cvt_fp16<<<(DIMC * DIMC) / 1024, 256>>>(Wfc, wfh, DIMC * DIMC);

    // 1) qkv = X @ Wqkv^T  (8192 x 3072), fp16 MMA, fp16 out
    gemm_h<true><<<dim3(3 * DIMC / 128, MROWS / 128), 256, GSMEM>>>(xh, wqh, qkvh, nullptr, 3 * DIMC);

    // 2) flash attention (fp16 in/out, 2-stage KV pipeline) -> xah
    attn_fa16<<<dim3(SEQN / 128, HEADS, BATCHB), 256>>>(qkvh, pmask, xah);

    // 3) out = xa @ Wfc^T + b_fc  (8192 x 1024), fp16 MMA, fp32 out
    gemm_h<false><<<dim3(DIMC / 128, MROWS / 128), 256, GSMEM>>>(xah, wfh, out, bfc, DIMC);
}

// round 14
// speedup vs baseline: 1.2631x; 1.2631x over previous
#include <cuda_runtime.h>
#include <cuda_fp16.h>
#include <cstdint>

#define DIMC 1024
#define HEADS 16
#define DH 64
#define BATCHB 4
#define SEQN 2048
#define MROWS (BATCHB * SEQN)
#define SCALE 0.125f
#define LOG2E 1.4426950408889634f

// Scratch (no allocations allowed)
__device__ __half g_xh[(size_t)MROWS * DIMC];
__device__ __half g_wqh[(size_t)3 * DIMC * DIMC];
__device__ __half g_wfh[(size_t)DIMC * DIMC];
__device__ __half g_qkvh[(size_t)MROWS * 3 * DIMC];
__device__ __half g_xah[(size_t)MROWS * DIMC];

// ---------------- PTX helpers ----------------
__device__ __forceinline__ void mma16816(float* d, const uint32_t* a, uint32_t b0, uint32_t b1) {
    asm volatile(
        "mma.sync.aligned.m16n8k16.row.col.f32.f16.f16.f32 "
        "{%0,%1,%2,%3}, {%4,%5,%6,%7}, {%8,%9}, {%0,%1,%2,%3};"
        : "+f"(d[0]), "+f"(d[1]), "+f"(d[2]), "+f"(d[3])
        : "r"(a[0]), "r"(a[1]), "r"(a[2]), "r"(a[3]),
          "r"(b0), "r"(b1));
}
__device__ __forceinline__ void ldsm_x4(uint32_t* r, uint32_t addr) {
    asm volatile("ldmatrix.sync.aligned.m8n8.x4.shared.b16 {%0,%1,%2,%3}, [%4];"
                 : "=r"(r[0]), "=r"(r[1]), "=r"(r[2]), "=r"(r[3]) : "r"(addr));
}
__device__ __forceinline__ void ldsm_x4_t(uint32_t& r0, uint32_t& r1, uint32_t& r2, uint32_t& r3,
                                          uint32_t addr) {
    asm volatile("ldmatrix.sync.aligned.m8n8.x4.trans.shared.b16 {%0,%1,%2,%3}, [%4];"
                 : "=r"(r0), "=r"(r1), "=r"(r2), "=r"(r3) : "r"(addr));
}
__device__ __forceinline__ float ex2f(float x) {
    float y;
    asm("ex2.approx.ftz.f32 %0, %1;" : "=f"(y) : "f"(x));
    return y;
}
__device__ __forceinline__ uint32_t packh2(float lo, float hi) {
    __half2 h = __floats2half2_rn(lo, hi);
    return *(uint32_t*)&h;
}
__device__ __forceinline__ void cp16(uint32_t dst, const void* src) {
    asm volatile("cp.async.cg.shared.global [%0], [%1], 16;" :: "r"(dst), "l"(src) : "memory");
}
#define CP_COMMIT() asm volatile("cp.async.commit_group;" ::: "memory")
#define CP_WAIT0()  asm volatile("cp.async.wait_group 0;" ::: "memory")
#define CP_WAIT1()  asm volatile("cp.async.wait_group 1;" ::: "memory")

// ---------------------------------------------------------------------------
// Fused fp32 -> fp16 conversion for X, Wqkv, Wfc in ONE launch.
// ---------------------------------------------------------------------------
#define N_X  (MROWS * DIMC)            // 8388608
#define N_WQ (3 * DIMC * DIMC)         // 3145728
#define N_WF (DIMC * DIMC)             // 1048576
#define N_CVT (N_X + N_WQ + N_WF)      // 12582912

__global__ __launch_bounds__(256) void cvt_all(const float* __restrict__ x,
                                               const float* __restrict__ wq,
                                               const float* __restrict__ wf,
                                               __half* __restrict__ xh,
                                               __half* __restrict__ wqh,
                                               __half* __restrict__ wfh)
{
    int i = (blockIdx.x * 256 + threadIdx.x) * 4;
    if (i >= N_CVT) return;
    const float* src;
    __half* dst;
    int off;
    if (i < N_X)               { src = x;  dst = xh;  off = i; }
    else if (i < N_X + N_WQ)   { src = wq; dst = wqh; off = i - N_X; }
    else                       { src = wf; dst = wfh; off = i - N_X - N_WQ; }
    float4 v = *(const float4*)(src + off);
    uint2 o;
    o.x = packh2(v.x, v.y);
    o.y = packh2(v.z, v.w);
    *(uint2*)(dst + off) = o;
}

// ---------------------------------------------------------------------------
// fp16 GEMM (byte-exact R8 best-known): C[m,n] = sum_k A[m,k]*B[n,k] (+bias).
// Block 128x128, BK=32, 256 threads (8 warps as 2m x 4n), warp tile 64x32.
// 3-stage cp.async pipeline; per stage: A[128][40] | B[128][40] halves.
// ---------------------------------------------------------------------------
#define GST     20480   // bytes per stage (A 10240 + B 10240)
#define GSMEM   (3 * GST)

template <bool OUT_HALF>
__global__ __launch_bounds__(256) void gemm_h(const __half* __restrict__ A,
                                              const __half* __restrict__ B,
                                              void* __restrict__ Cout,
                                              const float* __restrict__ bias,
                                              int N)
{
    extern __shared__ unsigned char sm[];
    const uint32_t smb = (uint32_t)__cvta_generic_to_shared(sm);
    const int tid  = threadIdx.x;
    const int wid  = tid >> 5;
    const int lane = tid & 31;
    const int g    = lane >> 2;
    const int tg   = lane & 3;
    const int bm   = blockIdx.y * 128;
    const int bn   = blockIdx.x * 128;
    const int wm   = (wid >> 2) * 64;
    const int wn   = (wid & 3) * 32;

    const int r   = tid >> 1;
    const int ch0 = (tid & 1) * 2;
    const __half* Ap = A + (size_t)(bm + r) * DIMC + ch0 * 8;
    const __half* Bp = B + (size_t)(bn + r) * DIMC + ch0 * 8;
    const uint32_t dA = smb + (uint32_t)(r * 80 + ch0 * 16);
    const uint32_t dB = dA + 10240;

    float acc[4][4][4];
#pragma unroll
    for (int mt = 0; mt < 4; mt++)
#pragma unroll
        for (int nt = 0; nt < 4; nt++)
#pragma unroll
            for (int i = 0; i < 4; i++) acc[mt][nt][i] = 0.0f;

#pragma unroll
    for (int c = 0; c < 2; c++) {
        cp16(dA + c * GST,      Ap + c * 32);
        cp16(dA + c * GST + 16, Ap + c * 32 + 8);
        cp16(dB + c * GST,      Bp + c * 32);
        cp16(dB + c * GST + 16, Bp + c * 32 + 8);
        CP_COMMIT();
    }

    const uint32_t aoff = (uint32_t)((wm + (lane & 15)) * 80 + (lane >> 4) * 16);
    const uint32_t boff = (uint32_t)(10240 + (wn + (lane & 7) + (lane >> 4) * 8) * 80 +
                                     ((lane >> 3) & 1) * 16);

    for (int c = 0; c < 32; c++) {
        const int s = c % 3;
        if (c == 31) { CP_WAIT0(); } else { CP_WAIT1(); }
        __syncthreads();
        if (c + 2 < 32) {
            const int sn = (c + 2) % 3;
            const __half* sa = Ap + (c + 2) * 32;
            const __half* sb = Bp + (c + 2) * 32;
            cp16(dA + sn * GST,      sa);
            cp16(dA + sn * GST + 16, sa + 8);
            cp16(dB + sn * GST,      sb);
            cp16(dB + sn * GST + 16, sb + 8);
            CP_COMMIT();
        }
        const uint32_t sb32 = smb + (uint32_t)(s * GST);
#pragma unroll
        for (int ks = 0; ks < 2; ks++) {
            uint32_t af[4][4], bf[2][4];
#pragma unroll
            for (int mt = 0; mt < 4; mt++)
                ldsm_x4(af[mt], sb32 + aoff + mt * 1280 + ks * 32);
#pragma unroll
            for (int p = 0; p < 2; p++)
                ldsm_x4(bf[p], sb32 + boff + p * 1280 + ks * 32);
#pragma unroll
            for (int mt = 0; mt < 4; mt++)
#pragma unroll
                for (int nt = 0; nt < 4; nt++)
                    mma16816(acc[mt][nt], af[mt],
                             bf[nt >> 1][(nt & 1) * 2], bf[nt >> 1][(nt & 1) * 2 + 1]);
        }
    }

#pragma unroll
    for (int mt = 0; mt < 4; mt++) {
#pragma unroll
        for (int nt = 0; nt < 4; nt++) {
            const int row0 = bm + wm + mt * 16 + g;
            const int col  = bn + wn + nt * 8 + 2 * tg;
            if (OUT_HALF) {
                __half* C = (__half*)Cout;
                *(uint32_t*)&C[(size_t)row0 * N + col]       = packh2(acc[mt][nt][0], acc[mt][nt][1]);
                *(uint32_t*)&C[(size_t)(row0 + 8) * N + col] = packh2(acc[mt][nt][2], acc[mt][nt][3]);
            } else {
                float* C = (float*)Cout;
                float b0 = 0.0f, b1 = 0.0f;
                if (bias != nullptr) { b0 = bias[col]; b1 = bias[col + 1]; }
                float2 v0, v1;
                v0.x = acc[mt][nt][0] + b0; v0.y = acc[mt][nt][1] + b1;
                v1.x = acc[mt][nt][2] + b0; v1.y = acc[mt][nt][3] + b1;
                *(float2*)(C + (size_t)row0 * N + col)       = v0;
                *(float2*)(C + (size_t)(row0 + 8) * N + col) = v1;
            }
        }
    }
}

// ---------------------------------------------------------------------------
// Flash attention, fp16 MMA, 2-stage cp.async KV pipeline.
// NOW: 128 threads / 4 warps / 64 q-rows per CTA, 4 CTAs/SM
// (same 16 warps/SM but 4 decoupled barrier groups, finer wave tail).
// Inner loop identical to best-known kernel.
// ---------------------------------------------------------------------------
#define KVBUF 9216   // 64*72*2 bytes per buffer

__global__ __launch_bounds__(128, 4) void attn_fa16(const __half* __restrict__ qkvh,
                                                    const int* __restrict__ pmask,
                                                    __half* __restrict__ xout)
{
    __shared__ __half Ks[2][64][72];
    __shared__ __half Vs[2][64][72];
    __shared__ float  mb[2][64];

    const int t    = threadIdx.x;
    const int w    = t >> 5;          // 0..3
    const int lane = t & 31;
    const int g    = lane >> 2;
    const int tg   = lane & 3;
    const int h    = blockIdx.y;
    const int b    = blockIdx.z;
    const int qbase = blockIdx.x * 64;

    const float SC2 = SCALE * LOG2E;

    uint32_t qa[4][4];
    {
        const int qr = b * SEQN + qbase + w * 16 + g;
        const __half* q0 = qkvh + (size_t)qr * (3 * DIMC) + h * DH;
        const __half* q8 = q0 + (size_t)8 * (3 * DIMC);
#pragma unroll
        for (int kt = 0; kt < 4; kt++) {
            qa[kt][0] = *(const uint32_t*)(q0 + kt * 16 + 2 * tg);
            qa[kt][1] = *(const uint32_t*)(q8 + kt * 16 + 2 * tg);
            qa[kt][2] = *(const uint32_t*)(q0 + kt * 16 + 8 + 2 * tg);
            qa[kt][3] = *(const uint32_t*)(q8 + kt * 16 + 8 + 2 * tg);
        }
    }

    const int lr = ((lane >> 3) & 1) * 8 + (lane & 7);
    const int lc = (lane >> 4) * 8;
    const uint32_t kbase = (uint32_t)__cvta_generic_to_shared(&Ks[0][0][0]);
    const uint32_t vbase = (uint32_t)__cvta_generic_to_shared(&Vs[0][0][0]);

    float m0 = -1e30f, m1 = -1e30f, l0 = 0.0f, l1 = 0.0f;
    float of[8][4];
#pragma unroll
    for (int nt = 0; nt < 8; nt++)
#pragma unroll
        for (int i = 0; i < 4; i++) of[nt][i] = 0.0f;

    // KV staging: 128 threads, 2 per key-row; each stages 64B (4x16B) of K and V
    const int rk  = t >> 1;              // 0..63
    const int chk = (t & 1) * 4;         // chunk base (16B units)
    const uint32_t dK = kbase + (uint32_t)(rk * 144 + chk * 16);
    const uint32_t dV = vbase + (uint32_t)(rk * 144 + chk * 16);
    const __half* kvsrc = qkvh + (size_t)(b * SEQN + rk) * (3 * DIMC) + DIMC + h * DH + chk * 8;

    // prologue: stage tile 0 into buffer 0
#pragma unroll
    for (int i = 0; i < 4; i++) {
        cp16(dK + i * 16, kvsrc + i * 8);
        cp16(dV + i * 16, kvsrc + DIMC + i * 8);
    }
    CP_COMMIT();
    if (t < 64) mb[0][t] = (pmask[b * SEQN + t] > 0) ? -1e9f : 0.0f;

    for (int it = 0; it < SEQN / 64; it++) {
        const int cur = it & 1;
        const int nxt = cur ^ 1;
        const bool have_next = (it + 1 < SEQN / 64);

        __syncthreads();
        if (have_next) {
            const __half* src = kvsrc + (size_t)(it + 1) * 64 * (3 * DIMC);
            const uint32_t o = (uint32_t)(nxt * KVBUF);
#pragma unroll
            for (int i = 0; i < 4; i++) {
                cp16(dK + o + i * 16, src + i * 8);
                cp16(dV + o + i * 16, src + DIMC + i * 8);
            }
            CP_COMMIT();
            if (t < 64) mb[nxt][t] = (pmask[b * SEQN + (it + 1) * 64 + t] > 0) ? -1e9f : 0.0f;
        }
        if (have_next) { CP_WAIT1(); } else { CP_WAIT0(); }
        __syncthreads();

        float sf[8][4];
#pragma unroll
        for (int nt = 0; nt < 8; nt++)
#pragma unroll
            for (int i = 0; i < 4; i++) sf[nt][i] = 0.0f;
#pragma unroll
        for (int kt = 0; kt < 4; kt++) {
#pragma unroll
            for (int nt = 0; nt < 8; nt++) {
                uint32_t kb0 = *(const uint32_t*)&Ks[cur][8 * nt + g][16 * kt + 2 * tg];
                uint32_t kb1 = *(const uint32_t*)&Ks[cur][8 * nt + g][16 * kt + 2 * tg + 8];
                mma16816(sf[nt], qa[kt], kb0, kb1);
            }
        }

        float mt0 = -1e30f, mt1 = -1e30f;
#pragma unroll
        for (int nt = 0; nt < 8; nt++) {
            float2 bb = *(const float2*)&mb[cur][8 * nt + 2 * tg];
            sf[nt][0] = fmaf(sf[nt][0], SC2, bb.x);
            sf[nt][1] = fmaf(sf[nt][1], SC2, bb.y);
            sf[nt][2] = fmaf(sf[nt][2], SC2, bb.x);
            sf[nt][3] = fmaf(sf[nt][3], SC2, bb.y);
            mt0 = fmaxf(mt0, fmaxf(sf[nt][0], sf[nt][1]));
            mt1 = fmaxf(mt1, fmaxf(sf[nt][2], sf[nt][3]));
        }
        mt0 = fmaxf(mt0, __shfl_xor_sync(0xffffffffu, mt0, 1));
        mt0 = fmaxf(mt0, __shfl_xor_sync(0xffffffffu, mt0, 2));
        mt1 = fmaxf(mt1, __shfl_xor_sync(0xffffffffu, mt1, 1));
        mt1 = fmaxf(mt1, __shfl_xor_sync(0xffffffffu, mt1, 2));

        const float mn0 = fmaxf(m0, mt0);
        const float mn1 = fmaxf(m1, mt1);
        const float alpha0 = ex2f(m0 - mn0);
        const float alpha1 = ex2f(m1 - mn1);
        m0 = mn0; m1 = mn1;

        float ls0 = 0.0f, ls1 = 0.0f;
        uint32_t pa[4][4];
#pragma unroll
        for (int nt = 0; nt < 8; nt++) {
            float p0 = ex2f(sf[nt][0] - mn0);
            float p1 = ex2f(sf[nt][1] - mn0);
            float p2 = ex2f(sf[nt][2] - mn1);
            float p3 = ex2f(sf[nt][3] - mn1);
            ls0 += p0 + p1;
            ls1 += p2 + p3;
            const int kt = nt >> 1;
            const int hi = (nt & 1) ? 2 : 0;
            pa[kt][hi + 0] = packh2(p0, p1);
            pa[kt][hi + 1] = packh2(p2, p3);
        }
        l0 = l0 * alpha0 + ls0;
        l1 = l1 * alpha1 + ls1;
#pragma unroll
        for (int nt = 0; nt < 8; nt++) {
            of[nt][0] *= alpha0;
            of[nt][1] *= alpha0;
            of[nt][2] *= alpha1;
            of[nt][3] *= alpha1;
        }

        const uint32_t vb = vbase + (uint32_t)(cur * KVBUF);
#pragma unroll
        for (int kt = 0; kt < 4; kt++) {
#pragma unroll
            for (int c = 0; c < 8; c += 2) {
                uint32_t r0, r1, r2, r3;
                uint32_t addr = vb + (uint32_t)(((16 * kt + lr) * 72 + lc + 8 * c) * 2);
                ldsm_x4_t(r0, r1, r2, r3, addr);
                mma16816(of[c],     pa[kt], r0, r1);
                mma16816(of[c + 1], pa[kt], r2, r3);
            }
        }
    }

    l0 += __shfl_xor_sync(0xffffffffu, l0, 1);
    l0 += __shfl_xor_sync(0xffffffffu, l0, 2);
    l1 += __shfl_xor_sync(0xffffffffu, l1, 1);
    l1 += __shfl_xor_sync(0xffffffffu, l1, 2);
    const float inv0 = 1.0f / l0;
    const float inv1 = 1.0f / l1;

    const int qr = qbase + w * 16 + g;
    __half* o0 = xout + ((size_t)(b * SEQN + qr) * HEADS + h) * DH;
    __half* o8 = xout + ((size_t)(b * SEQN + qr + 8) * HEADS + h) * DH;
#pragma unroll
    for (int nt = 0; nt < 8; nt++) {
        *(uint32_t*)&o0[8 * nt + 2 * tg] = packh2(of[nt][0] * inv0, of[nt][1] * inv0);
        *(uint32_t*)&o8[8 * nt + 2 * tg] = packh2(of[nt][2] * inv1, of[nt][3] * inv1);
    }
}

// ---------------------------------------------------------------------------
extern "C" void kernel_launch(void* const* d_in, const int* in_sizes, int n_in,
                              void* d_out, int out_size)
{
    const float* x     = (const float*)d_in[0];
    const float* Wqkv  = (const float*)d_in[1];
    const float* Wfc   = (const float*)d_in[2];
    const float* bfc   = (const float*)d_in[3];
    const int*   pmask = (const int*)d_in[4];
    float* out = (float*)d_out;

    __half *xh, *wqh, *wfh, *qkvh, *xah;
    cudaGetSymbolAddress((void**)&xh, g_xh);
    cudaGetSymbolAddress((void**)&wqh, g_wqh);
    cudaGetSymbolAddress((void**)&wfh, g_wfh);
    cudaGetSymbolAddress((void**)&qkvh, g_qkvh);
    cudaGetSymbolAddress((void**)&xah, g_xah);

    cudaFuncSetAttribute(gemm_h<true>,  cudaFuncAttributeMaxDynamicSharedMemorySize, GSMEM);
    cudaFuncSetAttribute(gemm_h<false>, cudaFuncAttributeMaxDynamicSharedMemorySize, GSMEM);

    // 0) fused fp32 -> fp16 conversion (single launch)
    cvt_all<<<(N_CVT / 4 + 255) / 256, 256>>>(x, Wqkv, Wfc, xh, wqh, wfh);

    // 1) qkv = X @ Wqkv^T  (8192 x 3072), fp16 MMA, fp16 out
    gemm_h<true><<<dim3(3 * DIMC / 128, MROWS / 128), 256, GSMEM>>>(xh, wqh, qkvh, nullptr, 3 * DIMC);

    // 2) flash attention (fp16 in/out, 4 CTAs/SM) -> xah
    attn_fa16<<<dim3(SEQN / 64, HEADS, BATCHB), 128>>>(qkvh, pmask, xah);

    // 3) out = xa @ Wfc^T + b_fc  (8192 x 1024), fp16 MMA, fp32 out
    gemm_h<false><<<dim3(DIMC / 128, MROWS / 128), 256, GSMEM>>>(xah, wfh, out, bfc, DIMC);
}

// round 15
// speedup vs baseline: 1.4515x; 1.1492x over previous
#include <cuda_runtime.h>
#include <cuda_fp16.h>
#include <cstdint>

#define DIMC 1024
#define HEADS 16
#define DH 64
#define BATCHB 4
#define SEQN 2048
#define MROWS (BATCHB * SEQN)
#define SCALE 0.125f
#define LOG2E 1.4426950408889634f

// Scratch (no allocations allowed)
__device__ __half g_xh[(size_t)MROWS * DIMC];
__device__ __half g_wqh[(size_t)3 * DIMC * DIMC];
__device__ __half g_wfh[(size_t)DIMC * DIMC];
__device__ __half g_qkvh[(size_t)MROWS * 3 * DIMC];
__device__ __half g_xah[(size_t)MROWS * DIMC];

// ---------------- PTX helpers ----------------
__device__ __forceinline__ void mma16816(float* d, const uint32_t* a, uint32_t b0, uint32_t b1) {
    asm volatile(
        "mma.sync.aligned.m16n8k16.row.col.f32.f16.f16.f32 "
        "{%0,%1,%2,%3}, {%4,%5,%6,%7}, {%8,%9}, {%0,%1,%2,%3};"
        : "+f"(d[0]), "+f"(d[1]), "+f"(d[2]), "+f"(d[3])
        : "r"(a[0]), "r"(a[1]), "r"(a[2]), "r"(a[3]),
          "r"(b0), "r"(b1));
}
__device__ __forceinline__ void ldsm_x4(uint32_t* r, uint32_t addr) {
    asm volatile("ldmatrix.sync.aligned.m8n8.x4.shared.b16 {%0,%1,%2,%3}, [%4];"
                 : "=r"(r[0]), "=r"(r[1]), "=r"(r[2]), "=r"(r[3]) : "r"(addr));
}
__device__ __forceinline__ void ldsm_x4_t(uint32_t& r0, uint32_t& r1, uint32_t& r2, uint32_t& r3,
                                          uint32_t addr) {
    asm volatile("ldmatrix.sync.aligned.m8n8.x4.trans.shared.b16 {%0,%1,%2,%3}, [%4];"
                 : "=r"(r0), "=r"(r1), "=r"(r2), "=r"(r3) : "r"(addr));
}
__device__ __forceinline__ float ex2f(float x) {
    float y;
    asm("ex2.approx.ftz.f32 %0, %1;" : "=f"(y) : "f"(x));
    return y;
}
__device__ __forceinline__ uint32_t packh2(float lo, float hi) {
    __half2 h = __floats2half2_rn(lo, hi);
    return *(uint32_t*)&h;
}
__device__ __forceinline__ void cp16(uint32_t dst, const void* src) {
    asm volatile("cp.async.cg.shared.global [%0], [%1], 16;" :: "r"(dst), "l"(src) : "memory");
}
#define CP_COMMIT() asm volatile("cp.async.commit_group;" ::: "memory")
#define CP_WAIT0()  asm volatile("cp.async.wait_group 0;" ::: "memory")
#define CP_WAIT1()  asm volatile("cp.async.wait_group 1;" ::: "memory")

// ---------------------------------------------------------------------------
// Fused fp32 -> fp16 conversion for X, Wqkv, Wfc in ONE launch.
// ---------------------------------------------------------------------------
#define N_X  (MROWS * DIMC)
#define N_WQ (3 * DIMC * DIMC)
#define N_WF (DIMC * DIMC)
#define N_CVT (N_X + N_WQ + N_WF)

__global__ __launch_bounds__(256) void cvt_all(const float* __restrict__ x,
                                               const float* __restrict__ wq,
                                               const float* __restrict__ wf,
                                               __half* __restrict__ xh,
                                               __half* __restrict__ wqh,
                                               __half* __restrict__ wfh)
{
    int i = (blockIdx.x * 256 + threadIdx.x) * 4;
    if (i >= N_CVT) return;
    const float* src;
    __half* dst;
    int off;
    if (i < N_X)             { src = x;  dst = xh;  off = i; }
    else if (i < N_X + N_WQ) { src = wq; dst = wqh; off = i - N_X; }
    else                     { src = wf; dst = wfh; off = i - N_X - N_WQ; }
    float4 v = *(const float4*)(src + off);
    uint2 o;
    o.x = packh2(v.x, v.y);
    o.y = packh2(v.z, v.w);
    *(uint2*)(dst + off) = o;
}

// ---------------------------------------------------------------------------
// fp16 GEMM (byte-exact R8 best-known): C[m,n] = sum_k A[m,k]*B[n,k] (+bias).
// Block 128x128, BK=32, 256 threads (8 warps as 2m x 4n), warp tile 64x32.
// 3-stage cp.async pipeline; per stage: A[128][40] | B[128][40] halves.
// ---------------------------------------------------------------------------
#define GST     20480
#define GSMEM   (3 * GST)

template <bool OUT_HALF>
__global__ __launch_bounds__(256) void gemm_h(const __half* __restrict__ A,
                                              const __half* __restrict__ B,
                                              void* __restrict__ Cout,
                                              const float* __restrict__ bias,
                                              int N)
{
    extern __shared__ unsigned char sm[];
    const uint32_t smb = (uint32_t)__cvta_generic_to_shared(sm);
    const int tid  = threadIdx.x;
    const int wid  = tid >> 5;
    const int lane = tid & 31;
    const int g    = lane >> 2;
    const int tg   = lane & 3;
    const int bm   = blockIdx.y * 128;
    const int bn   = blockIdx.x * 128;
    const int wm   = (wid >> 2) * 64;
    const int wn   = (wid & 3) * 32;

    const int r   = tid >> 1;
    const int ch0 = (tid & 1) * 2;
    const __half* Ap = A + (size_t)(bm + r) * DIMC + ch0 * 8;
    const __half* Bp = B + (size_t)(bn + r) * DIMC + ch0 * 8;
    const uint32_t dA = smb + (uint32_t)(r * 80 + ch0 * 16);
    const uint32_t dB = dA + 10240;

    float acc[4][4][4];
#pragma unroll
    for (int mt = 0; mt < 4; mt++)
#pragma unroll
        for (int nt = 0; nt < 4; nt++)
#pragma unroll
            for (int i = 0; i < 4; i++) acc[mt][nt][i] = 0.0f;

#pragma unroll
    for (int c = 0; c < 2; c++) {
        cp16(dA + c * GST,      Ap + c * 32);
        cp16(dA + c * GST + 16, Ap + c * 32 + 8);
        cp16(dB + c * GST,      Bp + c * 32);
        cp16(dB + c * GST + 16, Bp + c * 32 + 8);
        CP_COMMIT();
    }

    const uint32_t aoff = (uint32_t)((wm + (lane & 15)) * 80 + (lane >> 4) * 16);
    const uint32_t boff = (uint32_t)(10240 + (wn + (lane & 7) + (lane >> 4) * 8) * 80 +
                                     ((lane >> 3) & 1) * 16);

    for (int c = 0; c < 32; c++) {
        const int s = c % 3;
        if (c == 31) { CP_WAIT0(); } else { CP_WAIT1(); }
        __syncthreads();
        if (c + 2 < 32) {
            const int sn = (c + 2) % 3;
            const __half* sa = Ap + (c + 2) * 32;
            const __half* sb = Bp + (c + 2) * 32;
            cp16(dA + sn * GST,      sa);
            cp16(dA + sn * GST + 16, sa + 8);
            cp16(dB + sn * GST,      sb);
            cp16(dB + sn * GST + 16, sb + 8);
            CP_COMMIT();
        }
        const uint32_t sb32 = smb + (uint32_t)(s * GST);
#pragma unroll
        for (int ks = 0; ks < 2; ks++) {
            uint32_t af[4][4], bf[2][4];
#pragma unroll
            for (int mt = 0; mt < 4; mt++)
                ldsm_x4(af[mt], sb32 + aoff + mt * 1280 + ks * 32);
#pragma unroll
            for (int p = 0; p < 2; p++)
                ldsm_x4(bf[p], sb32 + boff + p * 1280 + ks * 32);
#pragma unroll
            for (int mt = 0; mt < 4; mt++)
#pragma unroll
                for (int nt = 0; nt < 4; nt++)
                    mma16816(acc[mt][nt], af[mt],
                             bf[nt >> 1][(nt & 1) * 2], bf[nt >> 1][(nt & 1) * 2 + 1]);
        }
    }

#pragma unroll
    for (int mt = 0; mt < 4; mt++) {
#pragma unroll
        for (int nt = 0; nt < 4; nt++) {
            const int row0 = bm + wm + mt * 16 + g;
            const int col  = bn + wn + nt * 8 + 2 * tg;
            if (OUT_HALF) {
                __half* C = (__half*)Cout;
                *(uint32_t*)&C[(size_t)row0 * N + col]       = packh2(acc[mt][nt][0], acc[mt][nt][1]);
                *(uint32_t*)&C[(size_t)(row0 + 8) * N + col] = packh2(acc[mt][nt][2], acc[mt][nt][3]);
            } else {
                float* C = (float*)Cout;
                float b0 = 0.0f, b1 = 0.0f;
                if (bias != nullptr) { b0 = bias[col]; b1 = bias[col + 1]; }
                float2 v0, v1;
                v0.x = acc[mt][nt][0] + b0; v0.y = acc[mt][nt][1] + b1;
                v1.x = acc[mt][nt][2] + b0; v1.y = acc[mt][nt][3] + b1;
                *(float2*)(C + (size_t)row0 * N + col)       = v0;
                *(float2*)(C + (size_t)(row0 + 8) * N + col) = v1;
            }
        }
    }
}

// ---------------------------------------------------------------------------
// Flash attention (R9 best-known structure: 256 thr, 128 q-rows, 2-stage KV
// cp.async pipeline). CHANGE: K fragments via ldmatrix.x4 (16/tile) instead
// of 64 scalar LDS — same data, same values, fewer smem ops.
// ---------------------------------------------------------------------------
#define KVBUF 9216   // 64*72*2 bytes per buffer

__global__ __launch_bounds__(256, 2) void attn_fa16(const __half* __restrict__ qkvh,
                                                    const int* __restrict__ pmask,
                                                    __half* __restrict__ xout)
{
    __shared__ __half Ks[2][64][72];
    __shared__ __half Vs[2][64][72];
    __shared__ float  mb[2][64];

    const int t    = threadIdx.x;
    const int w    = t >> 5;
    const int lane = t & 31;
    const int g    = lane >> 2;
    const int tg   = lane & 3;
    const int h    = blockIdx.y;
    const int b    = blockIdx.z;
    const int qbase = blockIdx.x * 128;

    const float SC2 = SCALE * LOG2E;

    uint32_t qa[4][4];
    {
        const int qr = b * SEQN + qbase + w * 16 + g;
        const __half* q0 = qkvh + (size_t)qr * (3 * DIMC) + h * DH;
        const __half* q8 = q0 + (size_t)8 * (3 * DIMC);
#pragma unroll
        for (int kt = 0; kt < 4; kt++) {
            qa[kt][0] = *(const uint32_t*)(q0 + kt * 16 + 2 * tg);
            qa[kt][1] = *(const uint32_t*)(q8 + kt * 16 + 2 * tg);
            qa[kt][2] = *(const uint32_t*)(q0 + kt * 16 + 8 + 2 * tg);
            qa[kt][3] = *(const uint32_t*)(q8 + kt * 16 + 8 + 2 * tg);
        }
    }

    const int lr = ((lane >> 3) & 1) * 8 + (lane & 7);
    const int lc = (lane >> 4) * 8;
    const uint32_t kbase = (uint32_t)__cvta_generic_to_shared(&Ks[0][0][0]);
    const uint32_t vbase = (uint32_t)__cvta_generic_to_shared(&Vs[0][0][0]);

    // K-fragment ldmatrix lane offset (same pattern as gemm boff, 144B rows):
    // lanes 0-7 -> n rows 0-7 @k0 (b0, nt even), 8-15 -> @k+8 (b1),
    // 16-23 -> n rows 8-15 @k0 (b0, nt odd), 24-31 -> @k+8 (b1)
    const uint32_t kfoff = (uint32_t)(((lane & 7) + ((lane >> 4) << 3)) * 144 +
                                      ((lane >> 3) & 1) * 16);

    float m0 = -1e30f, m1 = -1e30f, l0 = 0.0f, l1 = 0.0f;
    float of[8][4];
#pragma unroll
    for (int nt = 0; nt < 8; nt++)
#pragma unroll
        for (int i = 0; i < 4; i++) of[nt][i] = 0.0f;

    const int rk  = t >> 2;
    const int chk = (t & 3) * 2;
    const uint32_t dK = kbase + (uint32_t)(rk * 144 + chk * 16);
    const uint32_t dV = vbase + (uint32_t)(rk * 144 + chk * 16);
    const __half* kvsrc = qkvh + (size_t)(b * SEQN + rk) * (3 * DIMC) + DIMC + h * DH + chk * 8;

    // prologue: stage tile 0 into buffer 0
    cp16(dK,      kvsrc);
    cp16(dK + 16, kvsrc + 8);
    cp16(dV,      kvsrc + DIMC);
    cp16(dV + 16, kvsrc + DIMC + 8);
    CP_COMMIT();
    if (t < 64) mb[0][t] = (pmask[b * SEQN + t] > 0) ? -1e9f : 0.0f;

    for (int it = 0; it < SEQN / 64; it++) {
        const int cur = it & 1;
        const int nxt = cur ^ 1;
        const bool have_next = (it + 1 < SEQN / 64);

        __syncthreads();
        if (have_next) {
            const __half* src = kvsrc + (size_t)(it + 1) * 64 * (3 * DIMC);
            const uint32_t o = (uint32_t)(nxt * KVBUF);
            cp16(dK + o,      src);
            cp16(dK + o + 16, src + 8);
            cp16(dV + o,      src + DIMC);
            cp16(dV + o + 16, src + DIMC + 8);
            CP_COMMIT();
            if (t < 64) mb[nxt][t] = (pmask[b * SEQN + (it + 1) * 64 + t] > 0) ? -1e9f : 0.0f;
        }
        if (have_next) { CP_WAIT1(); } else { CP_WAIT0(); }
        __syncthreads();

        // ---- S = Q K^T, K fragments via ldmatrix.x4 ----
        float sf[8][4];
#pragma unroll
        for (int nt = 0; nt < 8; nt++)
#pragma unroll
            for (int i = 0; i < 4; i++) sf[nt][i] = 0.0f;

        const uint32_t kfb = kbase + (uint32_t)(cur * KVBUF) + kfoff;
#pragma unroll
        for (int kt = 0; kt < 4; kt++) {
#pragma unroll
            for (int p = 0; p < 4; p++) {       // p covers keys 16p..16p+15 (nt = 2p, 2p+1)
                uint32_t bf[4];
                ldsm_x4(bf, kfb + p * 2304 + kt * 32);
                mma16816(sf[2 * p],     qa[kt], bf[0], bf[1]);
                mma16816(sf[2 * p + 1], qa[kt], bf[2], bf[3]);
            }
        }

        float mt0 = -1e30f, mt1 = -1e30f;
#pragma unroll
        for (int nt = 0; nt < 8; nt++) {
            float2 bb = *(const float2*)&mb[cur][8 * nt + 2 * tg];
            sf[nt][0] = fmaf(sf[nt][0], SC2, bb.x);
            sf[nt][1] = fmaf(sf[nt][1], SC2, bb.y);
            sf[nt][2] = fmaf(sf[nt][2], SC2, bb.x);
            sf[nt][3] = fmaf(sf[nt][3], SC2, bb.y);
            mt0 = fmaxf(mt0, fmaxf(sf[nt][0], sf[nt][1]));
            mt1 = fmaxf(mt1, fmaxf(sf[nt][2], sf[nt][3]));
        }
        mt0 = fmaxf(mt0, __shfl_xor_sync(0xffffffffu, mt0, 1));
        mt0 = fmaxf(mt0, __shfl_xor_sync(0xffffffffu, mt0, 2));
        mt1 = fmaxf(mt1, __shfl_xor_sync(0xffffffffu, mt1, 1));
        mt1 = fmaxf(mt1, __shfl_xor_sync(0xffffffffu, mt1, 2));

        const float mn0 = fmaxf(m0, mt0);
        const float mn1 = fmaxf(m1, mt1);
        const float alpha0 = ex2f(m0 - mn0);
        const float alpha1 = ex2f(m1 - mn1);
        m0 = mn0; m1 = mn1;

        float ls0 = 0.0f, ls1 = 0.0f;
        uint32_t pa[4][4];
#pragma unroll
        for (int nt = 0; nt < 8; nt++) {
            float p0 = ex2f(sf[nt][0] - mn0);
            float p1 = ex2f(sf[nt][1] - mn0);
            float p2 = ex2f(sf[nt][2] - mn1);
            float p3 = ex2f(sf[nt][3] - mn1);
            ls0 += p0 + p1;
            ls1 += p2 + p3;
            const int kt = nt >> 1;
            const int hi = (nt & 1) ? 2 : 0;
            pa[kt][hi + 0] = packh2(p0, p1);
            pa[kt][hi + 1] = packh2(p2, p3);
        }
        l0 = l0 * alpha0 + ls0;
        l1 = l1 * alpha1 + ls1;
#pragma unroll
        for (int nt = 0; nt < 8; nt++) {
            of[nt][0] *= alpha0;
            of[nt][1] *= alpha0;
            of[nt][2] *= alpha1;
            of[nt][3] *= alpha1;
        }

        const uint32_t vb = vbase + (uint32_t)(cur * KVBUF);
#pragma unroll
        for (int kt = 0; kt < 4; kt++) {
#pragma unroll
            for (int c = 0; c < 8; c += 2) {
                uint32_t r0, r1, r2, r3;
                uint32_t addr = vb + (uint32_t)(((16 * kt + lr) * 72 + lc + 8 * c) * 2);
                ldsm_x4_t(r0, r1, r2, r3, addr);
                mma16816(of[c],     pa[kt], r0, r1);
                mma16816(of[c + 1], pa[kt], r2, r3);
            }
        }
    }

    l0 += __shfl_xor_sync(0xffffffffu, l0, 1);
    l0 += __shfl_xor_sync(0xffffffffu, l0, 2);
    l1 += __shfl_xor_sync(0xffffffffu, l1, 1);
    l1 += __shfl_xor_sync(0xffffffffu, l1, 2);
    const float inv0 = 1.0f / l0;
    const float inv1 = 1.0f / l1;

    const int qr = qbase + w * 16 + g;
    __half* o0 = xout + ((size_t)(b * SEQN + qr) * HEADS + h) * DH;
    __half* o8 = xout + ((size_t)(b * SEQN + qr + 8) * HEADS + h) * DH;
#pragma unroll
    for (int nt = 0; nt < 8; nt++) {
        *(uint32_t*)&o0[8 * nt + 2 * tg] = packh2(of[nt][0] * inv0, of[nt][1] * inv0);
        *(uint32_t*)&o8[8 * nt + 2 * tg] = packh2(of[nt][2] * inv1, of[nt][3] * inv1);
    }
}

// ---------------------------------------------------------------------------
extern "C" void kernel_launch(void* const* d_in, const int* in_sizes, int n_in,
                              void* d_out, int out_size)
{
    const float* x     = (const float*)d_in[0];
    const float* Wqkv  = (const float*)d_in[1];
    const float* Wfc   = (const float*)d_in[2];
    const float* bfc   = (const float*)d_in[3];
    const int*   pmask = (const int*)d_in[4];
    float* out = (float*)d_out;

    __half *xh, *wqh, *wfh, *qkvh, *xah;
    cudaGetSymbolAddress((void**)&xh, g_xh);
    cudaGetSymbolAddress((void**)&wqh, g_wqh);
    cudaGetSymbolAddress((void**)&wfh, g_wfh);
    cudaGetSymbolAddress((void**)&qkvh, g_qkvh);
    cudaGetSymbolAddress((void**)&xah, g_xah);

    cudaFuncSetAttribute(gemm_h<true>,  cudaFuncAttributeMaxDynamicSharedMemorySize, GSMEM);
    cudaFuncSetAttribute(gemm_h<false>, cudaFuncAttributeMaxDynamicSharedMemorySize, GSMEM);

    // 0) fused fp32 -> fp16 conversion (single launch)
    cvt_all<<<(N_CVT / 4 + 255) / 256, 256>>>(x, Wqkv, Wfc, xh, wqh, wfh);

    // 1) qkv = X @ Wqkv^T  (8192 x 3072), fp16 MMA, fp16 out
    gemm_h<true><<<dim3(3 * DIMC / 128, MROWS / 128), 256, GSMEM>>>(xh, wqh, qkvh, nullptr, 3 * DIMC);

    // 2) flash attention (fp16 in/out, 2-stage KV pipeline, ldmatrix K-frags)
    attn_fa16<<<dim3(SEQN / 128, HEADS, BATCHB), 256>>>(qkvh, pmask, xah);

    // 3) out = xa @ Wfc^T + b_fc  (8192 x 1024), fp16 MMA, fp32 out
    gemm_h<false><<<dim3(DIMC / 128, MROWS / 128), 256, GSMEM>>>(xah, wfh, out, bfc, DIMC);
}

// round 16
// speedup vs baseline: 1.4989x; 1.0326x over previous
#include <cuda_runtime.h>
#include <cuda_fp16.h>
#include <cstdint>

#define DIMC 1024
#define HEADS 16
#define DH 64
#define BATCHB 4
#define SEQN 2048
#define MROWS (BATCHB * SEQN)
#define SCALE 0.125f
#define LOG2E 1.4426950408889634f

// Scratch (no allocations allowed)
__device__ __half g_xh[(size_t)MROWS * DIMC];
__device__ __half g_wqh[(size_t)3 * DIMC * DIMC];
__device__ __half g_wfh[(size_t)DIMC * DIMC];
__device__ __half g_qkvh[(size_t)MROWS * 3 * DIMC];
__device__ __half g_xah[(size_t)MROWS * DIMC];

// ---------------- PTX helpers ----------------
__device__ __forceinline__ void mma16816(float* d, const uint32_t* a, uint32_t b0, uint32_t b1) {
    asm volatile(
        "mma.sync.aligned.m16n8k16.row.col.f32.f16.f16.f32 "
        "{%0,%1,%2,%3}, {%4,%5,%6,%7}, {%8,%9}, {%0,%1,%2,%3};"
        : "+f"(d[0]), "+f"(d[1]), "+f"(d[2]), "+f"(d[3])
        : "r"(a[0]), "r"(a[1]), "r"(a[2]), "r"(a[3]),
          "r"(b0), "r"(b1));
}
__device__ __forceinline__ void ldsm_x4(uint32_t* r, uint32_t addr) {
    asm volatile("ldmatrix.sync.aligned.m8n8.x4.shared.b16 {%0,%1,%2,%3}, [%4];"
                 : "=r"(r[0]), "=r"(r[1]), "=r"(r[2]), "=r"(r[3]) : "r"(addr));
}
__device__ __forceinline__ void ldsm_x4_t(uint32_t& r0, uint32_t& r1, uint32_t& r2, uint32_t& r3,
                                          uint32_t addr) {
    asm volatile("ldmatrix.sync.aligned.m8n8.x4.trans.shared.b16 {%0,%1,%2,%3}, [%4];"
                 : "=r"(r0), "=r"(r1), "=r"(r2), "=r"(r3) : "r"(addr));
}
__device__ __forceinline__ float ex2f(float x) {
    float y;
    asm("ex2.approx.ftz.f32 %0, %1;" : "=f"(y) : "f"(x));
    return y;
}
__device__ __forceinline__ uint32_t packh2(float lo, float hi) {
    __half2 h = __floats2half2_rn(lo, hi);
    return *(uint32_t*)&h;
}
__device__ __forceinline__ void cp16(uint32_t dst, const void* src) {
    asm volatile("cp.async.cg.shared.global [%0], [%1], 16;" :: "r"(dst), "l"(src) : "memory");
}
#define CP_COMMIT() asm volatile("cp.async.commit_group;" ::: "memory")
#define CP_WAIT0()  asm volatile("cp.async.wait_group 0;" ::: "memory")
#define CP_WAIT1()  asm volatile("cp.async.wait_group 1;" ::: "memory")

// ---------------------------------------------------------------------------
// Fused fp32 -> fp16 conversion for X, Wqkv, Wfc in ONE launch.
// ---------------------------------------------------------------------------
#define N_X  (MROWS * DIMC)
#define N_WQ (3 * DIMC * DIMC)
#define N_WF (DIMC * DIMC)
#define N_CVT (N_X + N_WQ + N_WF)

__global__ __launch_bounds__(256) void cvt_all(const float* __restrict__ x,
                                               const float* __restrict__ wq,
                                               const float* __restrict__ wf,
                                               __half* __restrict__ xh,
                                               __half* __restrict__ wqh,
                                               __half* __restrict__ wfh)
{
    int i = (blockIdx.x * 256 + threadIdx.x) * 4;
    if (i >= N_CVT) return;
    const float* src;
    __half* dst;
    int off;
    if (i < N_X)             { src = x;  dst = xh;  off = i; }
    else if (i < N_X + N_WQ) { src = wq; dst = wqh; off = i - N_X; }
    else                     { src = wf; dst = wfh; off = i - N_X - N_WQ; }
    float4 v = *(const float4*)(src + off);
    uint2 o;
    o.x = packh2(v.x, v.y);
    o.y = packh2(v.z, v.w);
    *(uint2*)(dst + off) = o;
}

// ---------------------------------------------------------------------------
// fp16 GEMM (byte-exact R8 best-known): C[m,n] = sum_k A[m,k]*B[n,k] (+bias).
// Block 128x128, BK=32, 256 threads (8 warps as 2m x 4n), warp tile 64x32.
// 3-stage cp.async pipeline; per stage: A[128][40] | B[128][40] halves.
// ---------------------------------------------------------------------------
#define GST     20480
#define GSMEM   (3 * GST)

template <bool OUT_HALF>
__global__ __launch_bounds__(256) void gemm_h(const __half* __restrict__ A,
                                              const __half* __restrict__ B,
                                              void* __restrict__ Cout,
                                              const float* __restrict__ bias,
                                              int N)
{
    extern __shared__ unsigned char sm[];
    const uint32_t smb = (uint32_t)__cvta_generic_to_shared(sm);
    const int tid  = threadIdx.x;
    const int wid  = tid >> 5;
    const int lane = tid & 31;
    const int g    = lane >> 2;
    const int tg   = lane & 3;
    const int bm   = blockIdx.y * 128;
    const int bn   = blockIdx.x * 128;
    const int wm   = (wid >> 2) * 64;
    const int wn   = (wid & 3) * 32;

    const int r   = tid >> 1;
    const int ch0 = (tid & 1) * 2;
    const __half* Ap = A + (size_t)(bm + r) * DIMC + ch0 * 8;
    const __half* Bp = B + (size_t)(bn + r) * DIMC + ch0 * 8;
    const uint32_t dA = smb + (uint32_t)(r * 80 + ch0 * 16);
    const uint32_t dB = dA + 10240;

    float acc[4][4][4];
#pragma unroll
    for (int mt = 0; mt < 4; mt++)
#pragma unroll
        for (int nt = 0; nt < 4; nt++)
#pragma unroll
            for (int i = 0; i < 4; i++) acc[mt][nt][i] = 0.0f;

#pragma unroll
    for (int c = 0; c < 2; c++) {
        cp16(dA + c * GST,      Ap + c * 32);
        cp16(dA + c * GST + 16, Ap + c * 32 + 8);
        cp16(dB + c * GST,      Bp + c * 32);
        cp16(dB + c * GST + 16, Bp + c * 32 + 8);
        CP_COMMIT();
    }

    const uint32_t aoff = (uint32_t)((wm + (lane & 15)) * 80 + (lane >> 4) * 16);
    const uint32_t boff = (uint32_t)(10240 + (wn + (lane & 7) + (lane >> 4) * 8) * 80 +
                                     ((lane >> 3) & 1) * 16);

    for (int c = 0; c < 32; c++) {
        const int s = c % 3;
        if (c == 31) { CP_WAIT0(); } else { CP_WAIT1(); }
        __syncthreads();
        if (c + 2 < 32) {
            const int sn = (c + 2) % 3;
            const __half* sa = Ap + (c + 2) * 32;
            const __half* sb = Bp + (c + 2) * 32;
            cp16(dA + sn * GST,      sa);
            cp16(dA + sn * GST + 16, sa + 8);
            cp16(dB + sn * GST,      sb);
            cp16(dB + sn * GST + 16, sb + 8);
            CP_COMMIT();
        }
        const uint32_t sb32 = smb + (uint32_t)(s * GST);
#pragma unroll
        for (int ks = 0; ks < 2; ks++) {
            uint32_t af[4][4], bf[2][4];
#pragma unroll
            for (int mt = 0; mt < 4; mt++)
                ldsm_x4(af[mt], sb32 + aoff + mt * 1280 + ks * 32);
#pragma unroll
            for (int p = 0; p < 2; p++)
                ldsm_x4(bf[p], sb32 + boff + p * 1280 + ks * 32);
#pragma unroll
            for (int mt = 0; mt < 4; mt++)
#pragma unroll
                for (int nt = 0; nt < 4; nt++)
                    mma16816(acc[mt][nt], af[mt],
                             bf[nt >> 1][(nt & 1) * 2], bf[nt >> 1][(nt & 1) * 2 + 1]);
        }
    }

#pragma unroll
    for (int mt = 0; mt < 4; mt++) {
#pragma unroll
        for (int nt = 0; nt < 4; nt++) {
            const int row0 = bm + wm + mt * 16 + g;
            const int col  = bn + wn + nt * 8 + 2 * tg;
            if (OUT_HALF) {
                __half* C = (__half*)Cout;
                *(uint32_t*)&C[(size_t)row0 * N + col]       = packh2(acc[mt][nt][0], acc[mt][nt][1]);
                *(uint32_t*)&C[(size_t)(row0 + 8) * N + col] = packh2(acc[mt][nt][2], acc[mt][nt][3]);
            } else {
                float* C = (float*)Cout;
                float b0 = 0.0f, b1 = 0.0f;
                if (bias != nullptr) { b0 = bias[col]; b1 = bias[col + 1]; }
                float2 v0, v1;
                v0.x = acc[mt][nt][0] + b0; v0.y = acc[mt][nt][1] + b1;
                v1.x = acc[mt][nt][2] + b0; v1.y = acc[mt][nt][3] + b1;
                *(float2*)(C + (size_t)row0 * N + col)       = v0;
                *(float2*)(C + (size_t)(row0 + 8) * N + col) = v1;
            }
        }
    }
}

// ---------------------------------------------------------------------------
// Flash attention (R15 winner + 3-buffer KV pipeline -> ONE sync per tile).
// 256 thr, 128 q-rows, ldmatrix K-frags. Prefetch distance 2.
// ---------------------------------------------------------------------------
#define KVBUF 9216   // 64*72*2 bytes per buffer

__global__ __launch_bounds__(256, 2) void attn_fa16(const __half* __restrict__ qkvh,
                                                    const int* __restrict__ pmask,
                                                    __half* __restrict__ xout)
{
    __shared__ __half Ks[3][64][72];
    __shared__ __half Vs[3][64][72];
    __shared__ float  mb[3][64];

    const int t    = threadIdx.x;
    const int w    = t >> 5;
    const int lane = t & 31;
    const int g    = lane >> 2;
    const int tg   = lane & 3;
    const int h    = blockIdx.y;
    const int b    = blockIdx.z;
    const int qbase = blockIdx.x * 128;

    const float SC2 = SCALE * LOG2E;

    uint32_t qa[4][4];
    {
        const int qr = b * SEQN + qbase + w * 16 + g;
        const __half* q0 = qkvh + (size_t)qr * (3 * DIMC) + h * DH;
        const __half* q8 = q0 + (size_t)8 * (3 * DIMC);
#pragma unroll
        for (int kt = 0; kt < 4; kt++) {
            qa[kt][0] = *(const uint32_t*)(q0 + kt * 16 + 2 * tg);
            qa[kt][1] = *(const uint32_t*)(q8 + kt * 16 + 2 * tg);
            qa[kt][2] = *(const uint32_t*)(q0 + kt * 16 + 8 + 2 * tg);
            qa[kt][3] = *(const uint32_t*)(q8 + kt * 16 + 8 + 2 * tg);
        }
    }

    const int lr = ((lane >> 3) & 1) * 8 + (lane & 7);
    const int lc = (lane >> 4) * 8;
    const uint32_t kbase = (uint32_t)__cvta_generic_to_shared(&Ks[0][0][0]);
    const uint32_t vbase = (uint32_t)__cvta_generic_to_shared(&Vs[0][0][0]);

    // K-fragment ldmatrix lane offset (144B rows, proven in R15)
    const uint32_t kfoff = (uint32_t)(((lane & 7) + ((lane >> 4) << 3)) * 144 +
                                      ((lane >> 3) & 1) * 16);

    float m0 = -1e30f, m1 = -1e30f, l0 = 0.0f, l1 = 0.0f;
    float of[8][4];
#pragma unroll
    for (int nt = 0; nt < 8; nt++)
#pragma unroll
        for (int i = 0; i < 4; i++) of[nt][i] = 0.0f;

    const int rk  = t >> 2;
    const int chk = (t & 3) * 2;
    const uint32_t dK = kbase + (uint32_t)(rk * 144 + chk * 16);
    const uint32_t dV = vbase + (uint32_t)(rk * 144 + chk * 16);
    const __half* kvsrc = qkvh + (size_t)(b * SEQN + rk) * (3 * DIMC) + DIMC + h * DH + chk * 8;

    // prologue: stage tiles 0 and 1 (separate commit groups)
#pragma unroll
    for (int pt = 0; pt < 2; pt++) {
        const __half* src = kvsrc + (size_t)pt * 64 * (3 * DIMC);
        const uint32_t o = (uint32_t)(pt * KVBUF);
        cp16(dK + o,      src);
        cp16(dK + o + 16, src + 8);
        cp16(dV + o,      src + DIMC);
        cp16(dV + o + 16, src + DIMC + 8);
        CP_COMMIT();
    }
    if (t < 64) {
        mb[0][t] = (pmask[b * SEQN + t] > 0) ? -1e9f : 0.0f;
        mb[1][t] = (pmask[b * SEQN + 64 + t] > 0) ? -1e9f : 0.0f;
    }

    for (int it = 0; it < SEQN / 64; it++) {
        const int cur = it % 3;
        const bool have2 = (it + 2 < SEQN / 64);

        if (it == SEQN / 64 - 1) { CP_WAIT0(); } else { CP_WAIT1(); }
        __syncthreads();   // single barrier: tile `cur` visible AND buffer (it+2)%3 freed

        if (have2) {
            const int nb = (it + 2) % 3;
            const __half* src = kvsrc + (size_t)(it + 2) * 64 * (3 * DIMC);
            const uint32_t o = (uint32_t)(nb * KVBUF);
            cp16(dK + o,      src);
            cp16(dK + o + 16, src + 8);
            cp16(dV + o,      src + DIMC);
            cp16(dV + o + 16, src + DIMC + 8);
            CP_COMMIT();
            if (t < 64) mb[nb][t] = (pmask[b * SEQN + (it + 2) * 64 + t] > 0) ? -1e9f : 0.0f;
        }

        // ---- S = Q K^T, K fragments via ldmatrix.x4 ----
        float sf[8][4];
#pragma unroll
        for (int nt = 0; nt < 8; nt++)
#pragma unroll
            for (int i = 0; i < 4; i++) sf[nt][i] = 0.0f;

        const uint32_t kfb = kbase + (uint32_t)(cur * KVBUF) + kfoff;
#pragma unroll
        for (int kt = 0; kt < 4; kt++) {
#pragma unroll
            for (int p = 0; p < 4; p++) {
                uint32_t bf[4];
                ldsm_x4(bf, kfb + p * 2304 + kt * 32);
                mma16816(sf[2 * p],     qa[kt], bf[0], bf[1]);
                mma16816(sf[2 * p + 1], qa[kt], bf[2], bf[3]);
            }
        }

        float mt0 = -1e30f, mt1 = -1e30f;
#pragma unroll
        for (int nt = 0; nt < 8; nt++) {
            float2 bb = *(const float2*)&mb[cur][8 * nt + 2 * tg];
            sf[nt][0] = fmaf(sf[nt][0], SC2, bb.x);
            sf[nt][1] = fmaf(sf[nt][1], SC2, bb.y);
            sf[nt][2] = fmaf(sf[nt][2], SC2, bb.x);
            sf[nt][3] = fmaf(sf[nt][3], SC2, bb.y);
            mt0 = fmaxf(mt0, fmaxf(sf[nt][0], sf[nt][1]));
            mt1 = fmaxf(mt1, fmaxf(sf[nt][2], sf[nt][3]));
        }
        mt0 = fmaxf(mt0, __shfl_xor_sync(0xffffffffu, mt0, 1));
        mt0 = fmaxf(mt0, __shfl_xor_sync(0xffffffffu, mt0, 2));
        mt1 = fmaxf(mt1, __shfl_xor_sync(0xffffffffu, mt1, 1));
        mt1 = fmaxf(mt1, __shfl_xor_sync(0xffffffffu, mt1, 2));

        const float mn0 = fmaxf(m0, mt0);
        const float mn1 = fmaxf(m1, mt1);
        const float alpha0 = ex2f(m0 - mn0);
        const float alpha1 = ex2f(m1 - mn1);
        m0 = mn0; m1 = mn1;

        float ls0 = 0.0f, ls1 = 0.0f;
        uint32_t pa[4][4];
#pragma unroll
        for (int nt = 0; nt < 8; nt++) {
            float p0 = ex2f(sf[nt][0] - mn0);
            float p1 = ex2f(sf[nt][1] - mn0);
            float p2 = ex2f(sf[nt][2] - mn1);
            float p3 = ex2f(sf[nt][3] - mn1);
            ls0 += p0 + p1;
            ls1 += p2 + p3;
            const int kt = nt >> 1;
            const int hi = (nt & 1) ? 2 : 0;
            pa[kt][hi + 0] = packh2(p0, p1);
            pa[kt][hi + 1] = packh2(p2, p3);
        }
        l0 = l0 * alpha0 + ls0;
        l1 = l1 * alpha1 + ls1;
#pragma unroll
        for (int nt = 0; nt < 8; nt++) {
            of[nt][0] *= alpha0;
            of[nt][1] *= alpha0;
            of[nt][2] *= alpha1;
            of[nt][3] *= alpha1;
        }

        const uint32_t vb = vbase + (uint32_t)(cur * KVBUF);
#pragma unroll
        for (int kt = 0; kt < 4; kt++) {
#pragma unroll
            for (int c = 0; c < 8; c += 2) {
                uint32_t r0, r1, r2, r3;
                uint32_t addr = vb + (uint32_t)(((16 * kt + lr) * 72 + lc + 8 * c) * 2);
                ldsm_x4_t(r0, r1, r2, r3, addr);
                mma16816(of[c],     pa[kt], r0, r1);
                mma16816(of[c + 1], pa[kt], r2, r3);
            }
        }
    }

    l0 += __shfl_xor_sync(0xffffffffu, l0, 1);
    l0 += __shfl_xor_sync(0xffffffffu, l0, 2);
    l1 += __shfl_xor_sync(0xffffffffu, l1, 1);
    l1 += __shfl_xor_sync(0xffffffffu, l1, 2);
    const float inv0 = 1.0f / l0;
    const float inv1 = 1.0f / l1;

    const int qr = qbase + w * 16 + g;
    __half* o0 = xout + ((size_t)(b * SEQN + qr) * HEADS + h) * DH;
    __half* o8 = xout + ((size_t)(b * SEQN + qr + 8) * HEADS + h) * DH;
#pragma unroll
    for (int nt = 0; nt < 8; nt++) {
        *(uint32_t*)&o0[8 * nt + 2 * tg] = packh2(of[nt][0] * inv0, of[nt][1] * inv0);
        *(uint32_t*)&o8[8 * nt + 2 * tg] = packh2(of[nt][2] * inv1, of[nt][3] * inv1);
    }
}

// ---------------------------------------------------------------------------
extern "C" void kernel_launch(void* const* d_in, const int* in_sizes, int n_in,
                              void* d_out, int out_size)
{
    const float* x     = (const float*)d_in[0];
    const float* Wqkv  = (const float*)d_in[1];
    const float* Wfc   = (const float*)d_in[2];
    const float* bfc   = (const float*)d_in[3];
    const int*   pmask = (const int*)d_in[4];
    float* out = (float*)d_out;

    __half *xh, *wqh, *wfh, *qkvh, *xah;
    cudaGetSymbolAddress((void**)&xh, g_xh);
    cudaGetSymbolAddress((void**)&wqh, g_wqh);
    cudaGetSymbolAddress((void**)&wfh, g_wfh);
    cudaGetSymbolAddress((void**)&qkvh, g_qkvh);
    cudaGetSymbolAddress((void**)&xah, g_xah);

    cudaFuncSetAttribute(gemm_h<true>,  cudaFuncAttributeMaxDynamicSharedMemorySize, GSMEM);
    cudaFuncSetAttribute(gemm_h<false>, cudaFuncAttributeMaxDynamicSharedMemorySize, GSMEM);

    // 0) fused fp32 -> fp16 conversion (single launch)
    cvt_all<<<(N_CVT / 4 + 255) / 256, 256>>>(x, Wqkv, Wfc, xh, wqh, wfh);

    // 1) qkv = X @ Wqkv^T  (8192 x 3072), fp16 MMA, fp16 out
    gemm_h<true><<<dim3(3 * DIMC / 128, MROWS / 128), 256, GSMEM>>>(xh, wqh, qkvh, nullptr, 3 * DIMC);

    // 2) flash attention (3-buffer KV pipeline, 1 sync/tile, ldmatrix K-frags)
    attn_fa16<<<dim3(SEQN / 128, HEADS, BATCHB), 256>>>(qkvh, pmask, xah);

    // 3) out = xa @ Wfc^T + b_fc  (8192 x 1024), fp16 MMA, fp32 out
    gemm_h<false><<<dim3(DIMC / 128, MROWS / 128), 256, GSMEM>>>(xah, wfh, out, bfc, DIMC);
}